// round 6
// baseline (speedup 1.0000x reference)
#include <cuda_runtime.h>

#define CC    10
#define NBIN  49
#define HH    34
#define WW    34
#define HW    (HH * WW)          // 1156
#define HW4   (HW / 4)           // 289
#define KDIM  (CC * NBIN)        // 490
#define NMAX  30000
#define BLK   512
#define TILES 4
#define KPAD  512                // scratch k rows (>= 16*32)
#define NPADMAX (NMAX + 128)

// Scratch (static device allocations are allowed)
__device__ float  g_out_t[KPAD * NPADMAX];   // [k][n], pitch NP (runtime, 128-aligned)
__device__ float4 g_ft8[NBIN * HW * 2];      // [bin][pos][c0..7] as 2x float4
__device__ float2 g_ft2[NBIN * HW];          // [bin][pos][c8..9]

// ---------------------------------------------------------------------------
// Kernel A: one block per bin. Stage slice [c][pos] (conflict-free float4),
// then emit channel-interleaved records with coalesced wide stores.
// ---------------------------------------------------------------------------
__global__ __launch_bounds__(512) void k_prep(const float* __restrict__ ft) {
    __shared__ float sm[CC * HW];            // 46.2 KB
    const int bin = blockIdx.x;
    float4* dst = reinterpret_cast<float4*>(sm);
    const float4* src = reinterpret_cast<const float4*>(ft);
    for (int i = threadIdx.x; i < CC * HW4; i += 512) {
        int c  = i / HW4;
        int p4 = i - c * HW4;
        dst[i] = src[(c * NBIN + bin) * HW4 + p4];
    }
    __syncthreads();
    for (int p = threadIdx.x; p < HW; p += 512) {
        float4 v0 = make_float4(sm[0 * HW + p], sm[1 * HW + p], sm[2 * HW + p], sm[3 * HW + p]);
        float4 v1 = make_float4(sm[4 * HW + p], sm[5 * HW + p], sm[6 * HW + p], sm[7 * HW + p]);
        float2 v2 = make_float2(sm[8 * HW + p], sm[9 * HW + p]);
        int idx = bin * HW + p;
        g_ft8[idx * 2 + 0] = v0;
        g_ft8[idx * 2 + 1] = v1;
        g_ft2[idx]         = v2;
    }
}

// ---------------------------------------------------------------------------
// Kernel B: one block = (bin, TILES roi-tiles). Separable 3x3 stencil +
// vectorized smem gather. (Unchanged from R5 except scratch pitch NP.)
// ---------------------------------------------------------------------------
__global__ __launch_bounds__(BLK) void k_roi(const float* __restrict__ rois, int N, int NP) {
    __shared__ float4 smA[HW * 2];   // [pos][c0..7]
    __shared__ float2 smB[HW];       // [pos][c8..9]
    const int bin = blockIdx.y;

    {   // stage: contiguous float4 copies, conflict-free
        const float4* s8 = g_ft8 + bin * HW * 2;
        const float4* s2 = reinterpret_cast<const float4*>(g_ft2 + bin * HW);
        float4* d2 = reinterpret_cast<float4*>(smB);
        for (int i = threadIdx.x; i < HW * 2; i += BLK) smA[i] = s8[i];
        for (int i = threadIdx.x; i < HW / 2; i += BLK) d2[i] = s2[i];
    }
    __syncthreads();

    const int ph = bin / 7, pw = bin % 7;

#pragma unroll 1
    for (int tile = 0; tile < TILES; tile++) {
        const int n = (blockIdx.x * TILES + tile) * BLK + threadIdx.x;
        if (n >= N) break;

        float rsw = __ldg(rois + n * 5 + 1) * 0.125f;
        float rsh = __ldg(rois + n * 5 + 2) * 0.125f;
        float rew = __ldg(rois + n * 5 + 3) * 0.125f;
        float reh = __ldg(rois + n * 5 + 4) * 0.125f;
        float rh = reh - rsh; rh = (rh > 0.1f) ? rh : 0.1f;
        float rw = rew - rsw; rw = (rw > 0.1f) ? rw : 0.1f;
        float bsh = rh / 7.0f, bsw = rw / 7.0f;
        float sub_h = bsh * 0.25f, sub_w = bsw * 0.25f;
        float hstart = floorf(rsh + (float)ph * bsh);
        float wstart = floorf(rsw + (float)pw * bsw);

        const int X0 = (int)fminf(fmaxf(wstart, 0.f), (float)(WW - 3));
        const int Y0 = (int)fminf(fmaxf(hstart, 0.f), (float)(HH - 3));

        // ---- Y pass ----
        float WY0 = 0.f, WY1 = 0.f, WY2 = 0.f;
        float CY0 = 0.f, CY1 = 0.f, CY2 = 0.f;
        float cntY = 0.f;
#pragma unroll
        for (int ih = 0; ih < 4; ih++) {
            float h = hstart + ((float)ih + 0.5f) * sub_h;
            bool hok = (h > -1.f) && (h < (float)HH);
            float y1f = floorf(h), y2f = ceilf(h);
            bool yv = ((y1f >= 0.f) && (y1f < (float)HH)) ||
                      ((y2f >= 0.f) && (y2f < (float)HH));
            float y1c = fminf(fmaxf(y1f, 0.f), 33.f);
            float y2c = fminf(fmaxf(y2f, 0.f), 33.f);
            float dy = h - y1c;
            int ry1 = (int)y1c - Y0;
            int ry2 = (int)y2c - Y0;
            float hokf = hok ? 1.f : 0.f;
            cntY += hokf;
            float ay = hokf * (1.f - dy), by = hokf * dy;
            WY0 += ((ry1 == 0) ? ay : 0.f) + ((ry2 == 0) ? by : 0.f);
            WY1 += ((ry1 == 1) ? ay : 0.f) + ((ry2 == 1) ? by : 0.f);
            WY2 += ((ry1 == 2) ? ay : 0.f) + ((ry2 == 2) ? by : 0.f);
            float cy = (hok && yv) ? (1.f - dy) : 0.f;
            CY0 += (ry1 == 0) ? cy : 0.f;
            CY1 += (ry1 == 1) ? cy : 0.f;
            CY2 += (ry1 == 2) ? cy : 0.f;
        }

        // ---- X pass ----
        float WX0 = 0.f, WX1 = 0.f, WX2 = 0.f;
        float CX0 = 0.f, CX1 = 0.f, CX2 = 0.f;
        float cntX = 0.f;
#pragma unroll
        for (int iw = 0; iw < 4; iw++) {
            float w = wstart + ((float)iw + 0.5f) * sub_w;
            bool wok = (w > -1.f) && (w < (float)WW);
            float x1f = floorf(w), x2f = ceilf(w);
            bool badx = !((x1f >= 0.f) && (x1f < (float)WW)) ||
                        !((x2f >= 0.f) && (x2f < (float)WW));
            float x1c = fminf(fmaxf(x1f, 0.f), 33.f);
            float x2c = fminf(fmaxf(x2f, 0.f), 33.f);
            float dx = w - x1c;
            int cx1 = (int)x1c - X0;
            int cx2 = (int)x2c - X0;
            float wokf = wok ? 1.f : 0.f;
            cntX += wokf;
            float ax = wokf * (1.f - dx), bx = wokf * dx;
            WX0 += ((cx1 == 0) ? ax : 0.f) + ((cx2 == 0) ? bx : 0.f);
            WX1 += ((cx1 == 1) ? ax : 0.f) + ((cx2 == 1) ? bx : 0.f);
            WX2 += ((cx1 == 2) ? ax : 0.f) + ((cx2 == 2) ? bx : 0.f);
            float cx = (wok && badx) ? (1.f - dx) : 0.f;
            CX0 += (cx1 == 0) ? cx : 0.f;
            CX1 += (cx1 == 1) ? cx : 0.f;
            CX2 += (cx1 == 2) ? cx : 0.f;
        }

        // ---- combine + normalize ----
        float cnt = cntY * cntX;
        float inv = (cnt > 0.f) ? (1.f / cnt) : 1.f;
        float wy0 = WY0 * inv, wy1 = WY1 * inv, wy2 = WY2 * inv;
        float W00 = fmaf(wy0, WX0, -CY0 * CX0 * inv);
        float W01 = fmaf(wy0, WX1, -CY0 * CX1 * inv);
        float W02 = fmaf(wy0, WX2, -CY0 * CX2 * inv);
        float W10 = fmaf(wy1, WX0, -CY1 * CX0 * inv);
        float W11 = fmaf(wy1, WX1, -CY1 * CX1 * inv);
        float W12 = fmaf(wy1, WX2, -CY1 * CX2 * inv);
        float W20 = fmaf(wy2, WX0, -CY2 * CX0 * inv);
        float W21 = fmaf(wy2, WX1, -CY2 * CX1 * inv);
        float W22 = fmaf(wy2, WX2, -CY2 * CX2 * inv);

        float a0=0.f,a1=0.f,a2=0.f,a3=0.f,a4=0.f,a5=0.f,a6=0.f,a7=0.f,a8=0.f,a9=0.f;
        const int pbase = Y0 * WW + X0;

#define TEXEL(WGT, P) do {                                                  \
            float4 u0 = smA[(P) * 2];                                       \
            float4 u1 = smA[(P) * 2 + 1];                                   \
            float2 u2 = smB[(P)];                                           \
            a0 = fmaf((WGT), u0.x, a0); a1 = fmaf((WGT), u0.y, a1);         \
            a2 = fmaf((WGT), u0.z, a2); a3 = fmaf((WGT), u0.w, a3);         \
            a4 = fmaf((WGT), u1.x, a4); a5 = fmaf((WGT), u1.y, a5);         \
            a6 = fmaf((WGT), u1.z, a6); a7 = fmaf((WGT), u1.w, a7);         \
            a8 = fmaf((WGT), u2.x, a8); a9 = fmaf((WGT), u2.y, a9);         \
        } while (0)

        TEXEL(W00, pbase);
        TEXEL(W01, pbase + 1);
        TEXEL(W10, pbase + WW);
        TEXEL(W11, pbase + WW + 1);

        bool colx = (W02 != 0.f) || (W12 != 0.f) || (W22 != 0.f);
        bool rowx = (W20 != 0.f) || (W21 != 0.f) || (W22 != 0.f);
        if (colx) { TEXEL(W02, pbase + 2); TEXEL(W12, pbase + WW + 2); }
        if (rowx) { TEXEL(W20, pbase + 2 * WW); TEXEL(W21, pbase + 2 * WW + 1); }
        if (colx && rowx) { TEXEL(W22, pbase + 2 * WW + 2); }
#undef TEXEL

        // Coalesced store to scratch [c*49+bin][n] (pitch NP)
        g_out_t[(0 * NBIN + bin) * NP + n] = a0;
        g_out_t[(1 * NBIN + bin) * NP + n] = a1;
        g_out_t[(2 * NBIN + bin) * NP + n] = a2;
        g_out_t[(3 * NBIN + bin) * NP + n] = a3;
        g_out_t[(4 * NBIN + bin) * NP + n] = a4;
        g_out_t[(5 * NBIN + bin) * NP + n] = a5;
        g_out_t[(6 * NBIN + bin) * NP + n] = a6;
        g_out_t[(7 * NBIN + bin) * NP + n] = a7;
        g_out_t[(8 * NBIN + bin) * NP + n] = a8;
        g_out_t[(9 * NBIN + bin) * NP + n] = a9;
    }
}

// ---------------------------------------------------------------------------
// Kernel C: transpose scratch[k][n] -> out[n][k]. Tile 32k x 128n, 256 thr.
// Loads are UNGUARDED (scratch k-rows padded to KPAD, n padded to pitch NP),
// 4 independent float4 loads per thread. Stores guarded, float2.
// ---------------------------------------------------------------------------
__global__ __launch_bounds__(256) void k_transpose_out(float* __restrict__ out,
                                                       int N, int NP) {
    __shared__ float tile[32][133];
    const int n0 = blockIdx.x * 128;
    const int k0 = blockIdx.y * 32;
    const int tx = threadIdx.x & 31;     // n: 32 x float4 = 128
    const int ty = threadIdx.x >> 5;     // k: 8 rows per iter

#pragma unroll
    for (int i = 0; i < 4; i++) {
        int k = k0 + ty + 8 * i;
        float4 v = *reinterpret_cast<const float4*>(&g_out_t[(size_t)k * NP + n0 + tx * 4]);
        tile[ty + 8 * i][tx * 4 + 0] = v.x;
        tile[ty + 8 * i][tx * 4 + 1] = v.y;
        tile[ty + 8 * i][tx * 4 + 2] = v.z;
        tile[ty + 8 * i][tx * 4 + 3] = v.w;
    }
    __syncthreads();

    const int sx = threadIdx.x & 15;     // k: 16 x float2 = 32
    const int sy = threadIdx.x >> 4;     // n: 16 rows per iter
    const int k  = k0 + sx * 2;
    if (k < KDIM) {                       // KDIM even, k even -> k+1 ok too
#pragma unroll
        for (int i = 0; i < 8; i++) {
            int n = n0 + sy + 16 * i;
            if (n < N) {
                float2 v;
                v.x = tile[sx * 2 + 0][sy + 16 * i];
                v.y = tile[sx * 2 + 1][sy + 16 * i];
                *reinterpret_cast<float2*>(&out[(size_t)n * KDIM + k]) = v;
            }
        }
    }
}

// ---------------------------------------------------------------------------
extern "C" void kernel_launch(void* const* d_in, const int* in_sizes, int n_in,
                              void* d_out, int out_size) {
    const float* rois = (const float*)d_in[1];
    const float* ft   = (const float*)d_in[0];
    float*       out  = (float*)d_out;
    int N = in_sizes[1] / 5;
    if (N > NMAX) N = NMAX;
    int NP = (N + 127) & ~127;           // 128-aligned pitch, <= NPADMAX

    k_prep<<<NBIN, 512>>>(ft);

    dim3 gb((N + BLK * TILES - 1) / (BLK * TILES), NBIN);
    k_roi<<<gb, BLK>>>(rois, N, NP);

    dim3 gc(NP / 128, (KDIM + 31) / 32); // 16 k-tiles, rows < KPAD
    k_transpose_out<<<gc, 256>>>(out, N, NP);
}